// round 9
// baseline (speedup 1.0000x reference)
#include <cuda_runtime.h>
#include <cuda_bf16.h>
#include <cstdint>

// ---------------------------------------------------------------------------
// Problem constants
// ---------------------------------------------------------------------------
#define Bq 2
#define Tt 2048
#define Dd 1024
#define DCc 512
#define DMm 1536
#define Hh 16
#define DEe 4096
#define DGg 1024
#define Mrows (Bq * Tt)          // 4096
#define CHD (DCc / Hh)           // 32
#define MHD (DMm / Hh)           // 96

// ---------------------------------------------------------------------------
// Scratch (device globals; cudaMalloc is forbidden)
// ---------------------------------------------------------------------------
__device__ float g_x1[Mrows * Dd];
__device__ float g_q [Mrows * DCc];
__device__ float g_k [Mrows * DCc];
__device__ float g_v [Mrows * DMm];
__device__ float g_y [Mrows * DMm];
__device__ float g_xa[Mrows * Dd];
__device__ float g_x2[Mrows * Dd];
__device__ float g_e [Mrows * DEe];
__device__ float g_sg[Mrows * DGg];
__device__ float g_g [Mrows * DEe];

// ---------------------------------------------------------------------------
// helpers
// ---------------------------------------------------------------------------
__device__ __forceinline__ void mma_tf32(float* c, const uint32_t* a, const uint32_t* b) {
    asm volatile(
        "mma.sync.aligned.m16n8k8.row.col.f32.tf32.tf32.f32 "
        "{%0,%1,%2,%3}, {%4,%5,%6,%7}, {%8,%9}, {%0,%1,%2,%3};"
        : "+f"(c[0]), "+f"(c[1]), "+f"(c[2]), "+f"(c[3])
        : "r"(a[0]), "r"(a[1]), "r"(a[2]), "r"(a[3]), "r"(b[0]), "r"(b[1]));
}

__device__ __forceinline__ void cp_async16(void* smem, const void* gmem) {
    uint32_t s = (uint32_t)__cvta_generic_to_shared(smem);
    asm volatile("cp.async.cg.shared.global [%0], [%1], 16;" :: "r"(s), "l"(gmem));
}
__device__ __forceinline__ void cp_commit() {
    asm volatile("cp.async.commit_group;");
}
template <int N>
__device__ __forceinline__ void cp_wait() {
    asm volatile("cp.async.wait_group %0;" :: "n"(N));
}

__device__ __forceinline__ float epilogue_apply(float v, float resv, int mode) {
    if (mode == 1)      v += resv;
    else if (mode == 2) v = v / (1.f + __expf(-v));
    else if (mode == 3) v = 1.f / (1.f + __expf(-v));
    else if (mode == 4) {                       // v=acc+bias; res=e
        float gv = 1.f / (1.f + __expf(-v));
        float t  = resv * gv;
        v = t / (1.f + __expf(-t));
    }
    return v;
}

// ---------------------------------------------------------------------------
// LayerNorm (unchanged)
// ---------------------------------------------------------------------------
__global__ __launch_bounds__(256) void ln_kernel(
    const float* __restrict__ x, const float* __restrict__ w,
    const float* __restrict__ b, float* __restrict__ out)
{
    int row = blockIdx.x;
    int tid = threadIdx.x;
    const float* xr = x + (size_t)row * Dd;
    float4 v = *(const float4*)(xr + tid * 4);
    float s  = v.x + v.y + v.z + v.w;
    float sq = v.x*v.x + v.y*v.y + v.z*v.z + v.w*v.w;
    #pragma unroll
    for (int o = 16; o > 0; o >>= 1) {
        s  += __shfl_xor_sync(0xffffffffu, s,  o);
        sq += __shfl_xor_sync(0xffffffffu, sq, o);
    }
    __shared__ float ss[8], ssq[8];
    int wid = tid >> 5, lid = tid & 31;
    if (lid == 0) { ss[wid] = s; ssq[wid] = sq; }
    __syncthreads();
    s = 0.f; sq = 0.f;
    #pragma unroll
    for (int i = 0; i < 8; i++) { s += ss[i]; sq += ssq[i]; }
    float mu  = s * (1.f / Dd);
    float var = sq * (1.f / Dd) - mu * mu;
    float rs  = rsqrtf(var + 1e-5f);
    float4 wv = *(const float4*)(w + tid * 4);
    float4 bv = *(const float4*)(b + tid * 4);
    float4 o;
    o.x = (v.x - mu) * rs * wv.x + bv.x;
    o.y = (v.y - mu) * rs * wv.y + bv.y;
    o.z = (v.z - mu) * rs * wv.z + bv.z;
    o.w = (v.w - mu) * rs * wv.w + bv.w;
    *(float4*)(out + (size_t)row * Dd + tid * 4) = o;
}

// ---------------------------------------------------------------------------
// TF32 GEMM, 128x128x16 tile (round-7 proven kernel, verbatim).
// ---------------------------------------------------------------------------
#define AST 20
#define BST 136
#define NSTG 3

__global__ __launch_bounds__(256) void tgemm_kernel(
    const float* __restrict__ A, const float* __restrict__ W,
    const float* __restrict__ bias, const float* __restrict__ res,
    float* __restrict__ C, int M, int N, int K, int mode)
{
    __shared__ float As[NSTG][128][AST];
    __shared__ float Bs[NSTG][16][BST];

    int t = threadIdx.x;
    int bm = blockIdx.y * 128;
    int bn = blockIdx.x * 128;
    int lane = t & 31, wid = t >> 5;
    int r = lane >> 2, q = lane & 3;
    int m_base = (wid & 3) * 32;
    int n_base = (wid >> 2) * 64;

    int a_row0 = t >> 2;
    int a_kc   = (t & 3) * 4;
    int b_row0 = t >> 5;
    int b_col  = (t & 31) * 4;

    const int nk = K / 16;

    const float* Abase = A + (size_t)(bm + a_row0) * K + a_kc;
    const float* Abase2 = Abase + (size_t)64 * K;
    const float* Wbase = W + (size_t)b_row0 * N + bn + b_col;
    const float* Wbase2 = Wbase + (size_t)8 * N;

    float acc[2][8][4];
    #pragma unroll
    for (int i = 0; i < 2; i++)
        #pragma unroll
        for (int j = 0; j < 8; j++)
            #pragma unroll
            for (int c = 0; c < 4; c++) acc[i][j][c] = 0.f;

    #pragma unroll
    for (int s = 0; s < 2; s++) {
        int k0 = s * 16;
        cp_async16(&As[s][a_row0     ][a_kc], Abase  + k0);
        cp_async16(&As[s][a_row0 + 64][a_kc], Abase2 + k0);
        cp_async16(&Bs[s][b_row0     ][b_col], Wbase  + (size_t)k0 * N);
        cp_async16(&Bs[s][b_row0 + 8 ][b_col], Wbase2 + (size_t)k0 * N);
        cp_commit();
    }
    cp_wait<1>();
    __syncthreads();

    for (int kt = 0; kt < nk; kt++) {
        int buf = kt % NSTG;

        #pragma unroll
        for (int k8 = 0; k8 < 16; k8 += 8) {
            uint32_t a[2][4], b[8][2];
            #pragma unroll
            for (int mt = 0; mt < 2; mt++) {
                int m0 = m_base + mt * 16;
                a[mt][0] = __float_as_uint(As[buf][m0 + r    ][k8 + q]);
                a[mt][1] = __float_as_uint(As[buf][m0 + r + 8][k8 + q]);
                a[mt][2] = __float_as_uint(As[buf][m0 + r    ][k8 + q + 4]);
                a[mt][3] = __float_as_uint(As[buf][m0 + r + 8][k8 + q + 4]);
            }
            #pragma unroll
            for (int nt = 0; nt < 8; nt++) {
                int n0 = n_base + nt * 8;
                b[nt][0] = __float_as_uint(Bs[buf][k8 + q    ][n0 + r]);
                b[nt][1] = __float_as_uint(Bs[buf][k8 + q + 4][n0 + r]);
            }
            #pragma unroll
            for (int mt = 0; mt < 2; mt++)
                #pragma unroll
                for (int nt = 0; nt < 8; nt++)
                    mma_tf32(acc[mt][nt], a[mt], b[nt]);
        }

        if (kt + 2 < nk) {
            int s  = (kt + 2) % NSTG;
            int k0 = (kt + 2) * 16;
            cp_async16(&As[s][a_row0     ][a_kc], Abase  + k0);
            cp_async16(&As[s][a_row0 + 64][a_kc], Abase2 + k0);
            cp_async16(&Bs[s][b_row0     ][b_col], Wbase  + (size_t)k0 * N);
            cp_async16(&Bs[s][b_row0 + 8 ][b_col], Wbase2 + (size_t)k0 * N);
        }
        cp_commit();
        cp_wait<1>();
        __syncthreads();
    }

    #pragma unroll
    for (int mt = 0; mt < 2; mt++) {
        int row0 = bm + m_base + mt * 16 + r;
        #pragma unroll
        for (int nt = 0; nt < 8; nt++) {
            int col = bn + n_base + nt * 8 + q * 2;
            float b0 = bias[col], b1 = bias[col + 1];
            float r0 = 0.f, r1 = 0.f, r2 = 0.f, r3 = 0.f;
            if (mode == 1 || mode == 4) {
                r0 = res[(size_t)row0 * N + col];
                r1 = res[(size_t)row0 * N + col + 1];
                r2 = res[(size_t)(row0 + 8) * N + col];
                r3 = res[(size_t)(row0 + 8) * N + col + 1];
            }
            float v0 = epilogue_apply(acc[mt][nt][0] + b0, r0, mode);
            float v1 = epilogue_apply(acc[mt][nt][1] + b1, r1, mode);
            float v2 = epilogue_apply(acc[mt][nt][2] + b0, r2, mode);
            float v3 = epilogue_apply(acc[mt][nt][3] + b1, r3, mode);
            *(float2*)(C + (size_t)row0 * N + col)       = make_float2(v0, v1);
            *(float2*)(C + (size_t)(row0 + 8) * N + col) = make_float2(v2, v3);
        }
    }
}

// ---------------------------------------------------------------------------
// TF32 GEMM, 256x128x16 tile. 256 threads, warp tile 64x64.
// Better MMA/LDS ratio (32 MMA per 32 LDS per k8-step) and half the
// sync overhead per FLOP. M % 256 == 0.
// ---------------------------------------------------------------------------
#define AST6 20
#define GEMM256_SMEM ((NSTG * 256 * AST6 + NSTG * 16 * BST) * 4)   // 85.5 KB

__global__ __launch_bounds__(256) void tgemm256_kernel(
    const float* __restrict__ A, const float* __restrict__ W,
    const float* __restrict__ bias, const float* __restrict__ res,
    float* __restrict__ C, int M, int N, int K, int mode)
{
    extern __shared__ float smf[];
    float (*As)[256][AST6] = (float(*)[256][AST6])smf;
    float (*Bs)[16][BST]   = (float(*)[16][BST])(smf + NSTG * 256 * AST6);

    int t = threadIdx.x;
    int bm = blockIdx.y * 256;
    int bn = blockIdx.x * 128;
    int lane = t & 31, wid = t >> 5;
    int r = lane >> 2, q = lane & 3;
    int m_base = (wid & 3) * 64;     // 4 m-warps
    int n_base = (wid >> 2) * 64;    // 2 n-warps

    // A: thread t loads row t's 16-float k-slab (4 x cp.async16)
    // B: row t>>4 (0..15), cols (t&15)*8 (2 x cp.async16)
    int b_row = t >> 4;
    int b_col = (t & 15) * 8;

    const int nk = K / 16;

    const float* Abase = A + (size_t)(bm + t) * K;
    const float* Wbase = W + (size_t)b_row * N + bn + b_col;

    float acc[4][8][4];
    #pragma unroll
    for (int i = 0; i < 4; i++)
        #pragma unroll
        for (int j = 0; j < 8; j++)
            #pragma unroll
            for (int c = 0; c < 4; c++) acc[i][j][c] = 0.f;

    #pragma unroll
    for (int s = 0; s < 2; s++) {
        int k0 = s * 16;
        #pragma unroll
        for (int j = 0; j < 4; j++)
            cp_async16(&As[s][t][4 * j], Abase + k0 + 4 * j);
        cp_async16(&Bs[s][b_row][b_col    ], Wbase + (size_t)k0 * N);
        cp_async16(&Bs[s][b_row][b_col + 4], Wbase + (size_t)k0 * N + 4);
        cp_commit();
    }
    cp_wait<1>();
    __syncthreads();

    for (int kt = 0; kt < nk; kt++) {
        int buf = kt % NSTG;

        #pragma unroll
        for (int k8 = 0; k8 < 16; k8 += 8) {
            uint32_t a[4][4], b[8][2];
            #pragma unroll
            for (int mt = 0; mt < 4; mt++) {
                int m0 = m_base + mt * 16;
                a[mt][0] = __float_as_uint(As[buf][m0 + r    ][k8 + q]);
                a[mt][1] = __float_as_uint(As[buf][m0 + r + 8][k8 + q]);
                a[mt][2] = __float_as_uint(As[buf][m0 + r    ][k8 + q + 4]);
                a[mt][3] = __float_as_uint(As[buf][m0 + r + 8][k8 + q + 4]);
            }
            #pragma unroll
            for (int nt = 0; nt < 8; nt++) {
                int n0 = n_base + nt * 8;
                b[nt][0] = __float_as_uint(Bs[buf][k8 + q    ][n0 + r]);
                b[nt][1] = __float_as_uint(Bs[buf][k8 + q + 4][n0 + r]);
            }
            #pragma unroll
            for (int mt = 0; mt < 4; mt++)
                #pragma unroll
                for (int nt = 0; nt < 8; nt++)
                    mma_tf32(acc[mt][nt], a[mt], b[nt]);
        }

        if (kt + 2 < nk) {
            int s  = (kt + 2) % NSTG;
            int k0 = (kt + 2) * 16;
            #pragma unroll
            for (int j = 0; j < 4; j++)
                cp_async16(&As[s][t][4 * j], Abase + k0 + 4 * j);
            cp_async16(&Bs[s][b_row][b_col    ], Wbase + (size_t)k0 * N);
            cp_async16(&Bs[s][b_row][b_col + 4], Wbase + (size_t)k0 * N + 4);
        }
        cp_commit();
        cp_wait<1>();
        __syncthreads();
    }

    #pragma unroll
    for (int mt = 0; mt < 4; mt++) {
        int row0 = bm + m_base + mt * 16 + r;
        #pragma unroll
        for (int nt = 0; nt < 8; nt++) {
            int col = bn + n_base + nt * 8 + q * 2;
            float b0 = bias[col], b1 = bias[col + 1];
            float r0 = 0.f, r1 = 0.f, r2 = 0.f, r3 = 0.f;
            if (mode == 1 || mode == 4) {
                r0 = res[(size_t)row0 * N + col];
                r1 = res[(size_t)row0 * N + col + 1];
                r2 = res[(size_t)(row0 + 8) * N + col];
                r3 = res[(size_t)(row0 + 8) * N + col + 1];
            }
            float v0 = epilogue_apply(acc[mt][nt][0] + b0, r0, mode);
            float v1 = epilogue_apply(acc[mt][nt][1] + b1, r1, mode);
            float v2 = epilogue_apply(acc[mt][nt][2] + b0, r2, mode);
            float v3 = epilogue_apply(acc[mt][nt][3] + b1, r3, mode);
            *(float2*)(C + (size_t)row0 * N + col)       = make_float2(v0, v1);
            *(float2*)(C + (size_t)(row0 + 8) * N + col) = make_float2(v2, v3);
        }
    }
}

// ---------------------------------------------------------------------------
// TF32 MMA flash attention (unchanged from round 8 — cvt-free version)
// ---------------------------------------------------------------------------
#define AT_KST 36
#define AT_VST 68
#define AT_SST 68
#define ATTN_SMEM ((64*AT_KST + 96*AT_VST + 4*16*AT_SST) * 4)

__global__ __launch_bounds__(128) void attn_mma_kernel(
    const float* __restrict__ q, const float* __restrict__ k,
    const float* __restrict__ v, float* __restrict__ y)
{
    extern __shared__ float sm[];
    float* Ks = sm;
    float* Vs = Ks + 64 * AT_KST;
    float* Ss = Vs + 96 * AT_VST;

    int tid  = threadIdx.x;
    int wid  = tid >> 5, lane = tid & 31;
    int r    = lane >> 2, qd = lane & 3;
    int qt   = blockIdx.x;
    int bh   = blockIdx.y;
    int b    = bh >> 4, h = bh & 15;
    int q0   = qt * 64;
    int mrow = wid * 16;

    const float* qbase = q + (size_t)b * Tt * DCc + h * CHD;
    const float* kbase = k + (size_t)b * Tt * DCc + h * CHD;
    const float* vbase = v + (size_t)b * Tt * DMm + h * MHD;

    const float scale = 0.17677669529663687f;
    int grow0 = q0 + mrow + r;
    uint32_t qa[4][4];
    #pragma unroll
    for (int ks = 0; ks < 4; ks++) {
        qa[ks][0] = __float_as_uint(qbase[(size_t)grow0       * DCc + ks * 8 + qd    ] * scale);
        qa[ks][1] = __float_as_uint(qbase[(size_t)(grow0 + 8) * DCc + ks * 8 + qd    ] * scale);
        qa[ks][2] = __float_as_uint(qbase[(size_t)grow0       * DCc + ks * 8 + qd + 4] * scale);
        qa[ks][3] = __float_as_uint(qbase[(size_t)(grow0 + 8) * DCc + ks * 8 + qd + 4] * scale);
    }

    float m0 = -1e30f, m1 = -1e30f, l0 = 0.f, l1 = 0.f;
    float o[12][4];
    #pragma unroll
    for (int nt = 0; nt < 12; nt++)
        #pragma unroll
        for (int c = 0; c < 4; c++) o[nt][c] = 0.f;

    float* Sw = Ss + wid * 16 * AT_SST;

    for (int j = 0; j <= qt; j++) {
        int k0 = j * 64;
        __syncthreads();
        {
            int row = tid >> 1;
            int c0  = (tid & 1) * 16;
            const float* src = kbase + (size_t)(k0 + row) * DCc + c0;
            float* dst = &Ks[row * AT_KST + c0];
            #pragma unroll
            for (int jj = 0; jj < 4; jj++) {
                float4 f = *(const float4*)(src + jj * 4);
                *(float4*)(dst + jj * 4) = f;
            }
        }
        {
            #pragma unroll
            for (int it = 0; it < 12; it++) {
                int idx  = it * 128 + tid;
                int trow = idx / 24, c4 = idx % 24;
                float4 f = *(const float4*)(vbase + (size_t)(k0 + trow) * DMm + c4 * 4);
                Vs[(c4 * 4 + 0) * AT_VST + trow] = f.x;
                Vs[(c4 * 4 + 1) * AT_VST + trow] = f.y;
                Vs[(c4 * 4 + 2) * AT_VST + trow] = f.z;
                Vs[(c4 * 4 + 3) * AT_VST + trow] = f.w;
            }
        }
        __syncthreads();

        float sc[8][4];
        #pragma unroll
        for (int nt = 0; nt < 8; nt++)
            #pragma unroll
            for (int c = 0; c < 4; c++) sc[nt][c] = 0.f;
        #pragma unroll
        for (int ks = 0; ks < 4; ks++) {
            #pragma unroll
            for (int nt = 0; nt < 8; nt++) {
                uint32_t bb[2];
                bb[0] = __float_as_uint(Ks[(nt * 8 + r) * AT_KST + ks * 8 + qd    ]);
                bb[1] = __float_as_uint(Ks[(nt * 8 + r) * AT_KST + ks * 8 + qd + 4]);
                mma_tf32(sc[nt], qa[ks], bb);
            }
        }

        float mx0 = -1e30f, mx1 = -1e30f;
        #pragma unroll
        for (int nt = 0; nt < 8; nt++) {
            int c = k0 + nt * 8 + 2 * qd;
            if (c     > grow0    ) sc[nt][0] = -1e30f;
            if (c + 1 > grow0    ) sc[nt][1] = -1e30f;
            if (c     > grow0 + 8) sc[nt][2] = -1e30f;
            if (c + 1 > grow0 + 8) sc[nt][3] = -1e30f;
            mx0 = fmaxf(mx0, fmaxf(sc[nt][0], sc[nt][1]));
            mx1 = fmaxf(mx1, fmaxf(sc[nt][2], sc[nt][3]));
        }
        mx0 = fmaxf(mx0, __shfl_xor_sync(0xffffffffu, mx0, 1));
        mx0 = fmaxf(mx0, __shfl_xor_sync(0xffffffffu, mx0, 2));
        mx1 = fmaxf(mx1, __shfl_xor_sync(0xffffffffu, mx1, 1));
        mx1 = fmaxf(mx1, __shfl_xor_sync(0xffffffffu, mx1, 2));

        float mn0 = fmaxf(m0, mx0), mn1 = fmaxf(m1, mx1);
        float corr0 = __expf(m0 - mn0), corr1 = __expf(m1 - mn1);
        float s0 = 0.f, s1 = 0.f;
        #pragma unroll
        for (int nt = 0; nt < 8; nt++) {
            float p00 = __expf(sc[nt][0] - mn0);
            float p01 = __expf(sc[nt][1] - mn0);
            float p10 = __expf(sc[nt][2] - mn1);
            float p11 = __expf(sc[nt][3] - mn1);
            s0 += p00 + p01;
            s1 += p10 + p11;
            int cb = nt * 8 + 2 * qd;
            Sw[r * AT_SST + cb]           = p00;
            Sw[r * AT_SST + cb + 1]       = p01;
            Sw[(r + 8) * AT_SST + cb]     = p10;
            Sw[(r + 8) * AT_SST + cb + 1] = p11;
        }
        s0 += __shfl_xor_sync(0xffffffffu, s0, 1);
        s0 += __shfl_xor_sync(0xffffffffu, s0, 2);
        s1 += __shfl_xor_sync(0xffffffffu, s1, 1);
        s1 += __shfl_xor_sync(0xffffffffu, s1, 2);
        l0 = l0 * corr0 + s0;
        l1 = l1 * corr1 + s1;
        m0 = mn0; m1 = mn1;
        #pragma unroll
        for (int nt = 0; nt < 12; nt++) {
            o[nt][0] *= corr0; o[nt][1] *= corr0;
            o[nt][2] *= corr1; o[nt][3] *= corr1;
        }
        __syncwarp();

        #pragma unroll
        for (int ks = 0; ks < 8; ks++) {
            uint32_t pa[4];
            pa[0] = __float_as_uint(Sw[r       * AT_SST + ks * 8 + qd    ]);
            pa[1] = __float_as_uint(Sw[(r + 8) * AT_SST + ks * 8 + qd    ]);
            pa[2] = __float_as_uint(Sw[r       * AT_SST + ks * 8 + qd + 4]);
            pa[3] = __float_as_uint(Sw[(r + 8) * AT_SST + ks * 8 + qd + 4]);
            #pragma unroll
            for (int nt = 0; nt < 12; nt++) {
                uint32_t bb[2];
                bb[0] = __float_as_uint(Vs[(nt * 8 + r) * AT_VST + ks * 8 + qd    ]);
                bb[1] = __float_as_uint(Vs[(nt * 8 + r) * AT_VST + ks * 8 + qd + 4]);
                mma_tf32(o[nt], pa, bb);
            }
        }
        __syncwarp();
    }

    float inv0 = 1.f / l0, inv1 = 1.f / l1;
    float* yb = y + (size_t)b * Tt * DMm + h * MHD;
    #pragma unroll
    for (int nt = 0; nt < 12; nt++) {
        int cb = nt * 8 + 2 * qd;
        *(float2*)(yb + (size_t)grow0 * DMm + cb) =
            make_float2(o[nt][0] * inv0, o[nt][1] * inv0);
        *(float2*)(yb + (size_t)(grow0 + 8) * DMm + cb) =
            make_float2(o[nt][2] * inv1, o[nt][3] * inv1);
    }
}

// ---------------------------------------------------------------------------
// Host launcher
// ---------------------------------------------------------------------------
extern "C" void kernel_launch(void* const* d_in, const int* in_sizes, int n_in,
                              void* d_out, int out_size)
{
    const float* x     = (const float*)d_in[0];
    const float* ln1_w = (const float*)d_in[2];
    const float* ln1_b = (const float*)d_in[3];
    const float* wq    = (const float*)d_in[4];
    const float* bq    = (const float*)d_in[5];
    const float* wk    = (const float*)d_in[6];
    const float* bk    = (const float*)d_in[7];
    const float* wv    = (const float*)d_in[8];
    const float* bv    = (const float*)d_in[9];
    const float* wo    = (const float*)d_in[10];
    const float* bo    = (const float*)d_in[11];
    const float* ln2_w = (const float*)d_in[12];
    const float* ln2_b = (const float*)d_in[13];
    const float* we    = (const float*)d_in[14];
    const float* be    = (const float*)d_in[15];
    const float* wg    = (const float*)d_in[16];
    const float* bg    = (const float*)d_in[17];
    const float* wu    = (const float*)d_in[18];
    const float* bu    = (const float*)d_in[19];
    const float* wc    = (const float*)d_in[20];
    const float* bc    = (const float*)d_in[21];
    float* out = (float*)d_out;

    float *x1, *qp, *kp, *vp, *yp, *xa, *x2, *ep, *sg, *gp;
    cudaGetSymbolAddress((void**)&x1, g_x1);
    cudaGetSymbolAddress((void**)&qp, g_q);
    cudaGetSymbolAddress((void**)&kp, g_k);
    cudaGetSymbolAddress((void**)&vp, g_v);
    cudaGetSymbolAddress((void**)&yp, g_y);
    cudaGetSymbolAddress((void**)&xa, g_xa);
    cudaGetSymbolAddress((void**)&x2, g_x2);
    cudaGetSymbolAddress((void**)&ep, g_e);
    cudaGetSymbolAddress((void**)&sg, g_sg);
    cudaGetSymbolAddress((void**)&gp, g_g);

    cudaFuncSetAttribute(attn_mma_kernel,
                         cudaFuncAttributeMaxDynamicSharedMemorySize, ATTN_SMEM);
    cudaFuncSetAttribute(tgemm256_kernel,
                         cudaFuncAttributeMaxDynamicSharedMemorySize, GEMM256_SMEM);

    // 1) LN1
    ln_kernel<<<Mrows, 256>>>(x, ln1_w, ln1_b, x1);

    // 2) Q/K (small N -> 128-tile), V (256-tile)
    tgemm_kernel<<<dim3(DCc/128, Mrows/128), 256>>>(x1, wq, bq, nullptr, qp, Mrows, DCc, Dd, 0);
    tgemm_kernel<<<dim3(DCc/128, Mrows/128), 256>>>(x1, wk, bk, nullptr, kp, Mrows, DCc, Dd, 0);
    tgemm256_kernel<<<dim3(DMm/128, Mrows/256), 256, GEMM256_SMEM>>>(x1, wv, bv, nullptr, vp, Mrows, DMm, Dd, 0);

    // 3) causal attention (TF32 MMA)
    attn_mma_kernel<<<dim3(Tt/64, Bq*Hh), 128, ATTN_SMEM>>>(qp, kp, vp, yp);

    // 4) output projection + residual
    tgemm256_kernel<<<dim3(Dd/128, Mrows/256), 256, GEMM256_SMEM>>>(yp, wo, bo, x, xa, Mrows, Dd, DMm, 1);

    // 5) LN2
    ln_kernel<<<Mrows, 256>>>(xa, ln2_w, ln2_b, x2);

    // 6) e = x2@we + be
    tgemm256_kernel<<<dim3(DEe/128, Mrows/256), 256, GEMM256_SMEM>>>(x2, we, be, nullptr, ep, Mrows, DEe, Dd, 0);

    // 7) sg = silu(x2@wg + bg)
    tgemm256_kernel<<<dim3(DGg/128, Mrows/256), 256, GEMM256_SMEM>>>(x2, wg, bg, nullptr, sg, Mrows, DGg, Dd, 2);

    // 8) e = silu(e * sigmoid(sg@wu + bu))   [fused eg]
    tgemm256_kernel<<<dim3(DEe/128, Mrows/256), 256, GEMM256_SMEM>>>(sg, wu, bu, ep, ep, Mrows, DEe, DGg, 4);

    // 9) out = xa + e@wc + bc
    tgemm256_kernel<<<dim3(Dd/128, Mrows/256), 256, GEMM256_SMEM>>>(ep, wc, bc, xa, out, Mrows, Dd, DEe, 1);
}

// round 10
// speedup vs baseline: 1.3252x; 1.3252x over previous
#include <cuda_runtime.h>
#include <cuda_bf16.h>
#include <cstdint>

// ---------------------------------------------------------------------------
// Problem constants
// ---------------------------------------------------------------------------
#define Bq 2
#define Tt 2048
#define Dd 1024
#define DCc 512
#define DMm 1536
#define Hh 16
#define DEe 4096
#define DGg 1024
#define Mrows (Bq * Tt)          // 4096
#define CHD (DCc / Hh)           // 32
#define MHD (DMm / Hh)           // 96

// ---------------------------------------------------------------------------
// Scratch (device globals; cudaMalloc is forbidden)
// ---------------------------------------------------------------------------
__device__ float g_x1[Mrows * Dd];
__device__ float g_q [Mrows * DCc];
__device__ float g_k [Mrows * DCc];
__device__ float g_v [Mrows * DMm];
__device__ float g_y [Mrows * DMm];
__device__ float g_xa[Mrows * Dd];
__device__ float g_x2[Mrows * Dd];
__device__ float g_e [Mrows * DEe];
__device__ float g_sg[Mrows * DGg];

// ---------------------------------------------------------------------------
// helpers
// ---------------------------------------------------------------------------
__device__ __forceinline__ void mma_tf32(float* c, const uint32_t* a, const uint32_t* b) {
    asm volatile(
        "mma.sync.aligned.m16n8k8.row.col.f32.tf32.tf32.f32 "
        "{%0,%1,%2,%3}, {%4,%5,%6,%7}, {%8,%9}, {%0,%1,%2,%3};"
        : "+f"(c[0]), "+f"(c[1]), "+f"(c[2]), "+f"(c[3])
        : "r"(a[0]), "r"(a[1]), "r"(a[2]), "r"(a[3]), "r"(b[0]), "r"(b[1]));
}

__device__ __forceinline__ void cp_async16(void* smem, const void* gmem) {
    uint32_t s = (uint32_t)__cvta_generic_to_shared(smem);
    asm volatile("cp.async.cg.shared.global [%0], [%1], 16;" :: "r"(s), "l"(gmem));
}
__device__ __forceinline__ void cp_commit() {
    asm volatile("cp.async.commit_group;");
}
template <int N>
__device__ __forceinline__ void cp_wait() {
    asm volatile("cp.async.wait_group %0;" :: "n"(N));
}

__device__ __forceinline__ float epilogue_apply(float v, float resv, int mode) {
    if (mode == 1)      v += resv;
    else if (mode == 2) v = v / (1.f + __expf(-v));
    else if (mode == 3) v = 1.f / (1.f + __expf(-v));
    else if (mode == 4) {                       // v=acc+bias; res=e
        float gv = 1.f / (1.f + __expf(-v));
        float t  = resv * gv;
        v = t / (1.f + __expf(-t));
    }
    return v;
}

// ---------------------------------------------------------------------------
// LayerNorm (unchanged)
// ---------------------------------------------------------------------------
__global__ __launch_bounds__(256) void ln_kernel(
    const float* __restrict__ x, const float* __restrict__ w,
    const float* __restrict__ b, float* __restrict__ out)
{
    int row = blockIdx.x;
    int tid = threadIdx.x;
    const float* xr = x + (size_t)row * Dd;
    float4 v = *(const float4*)(xr + tid * 4);
    float s  = v.x + v.y + v.z + v.w;
    float sq = v.x*v.x + v.y*v.y + v.z*v.z + v.w*v.w;
    #pragma unroll
    for (int o = 16; o > 0; o >>= 1) {
        s  += __shfl_xor_sync(0xffffffffu, s,  o);
        sq += __shfl_xor_sync(0xffffffffu, sq, o);
    }
    __shared__ float ss[8], ssq[8];
    int wid = tid >> 5, lid = tid & 31;
    if (lid == 0) { ss[wid] = s; ssq[wid] = sq; }
    __syncthreads();
    s = 0.f; sq = 0.f;
    #pragma unroll
    for (int i = 0; i < 8; i++) { s += ss[i]; sq += ssq[i]; }
    float mu  = s * (1.f / Dd);
    float var = sq * (1.f / Dd) - mu * mu;
    float rs  = rsqrtf(var + 1e-5f);
    float4 wv = *(const float4*)(w + tid * 4);
    float4 bv = *(const float4*)(b + tid * 4);
    float4 o;
    o.x = (v.x - mu) * rs * wv.x + bv.x;
    o.y = (v.y - mu) * rs * wv.y + bv.y;
    o.z = (v.z - mu) * rs * wv.z + bv.z;
    o.w = (v.w - mu) * rs * wv.w + bv.w;
    *(float4*)(out + (size_t)row * Dd + tid * 4) = o;
}

// ---------------------------------------------------------------------------
// TF32 GEMM body, 128x128x16 tile (round-7 proven loop, factored).
// modes: 0 bias, 1 +res, 2 SiLU, 3 sigmoid, 4 fused e=silu(e*sigmoid(.))
// ---------------------------------------------------------------------------
#define AST 20
#define BST 136
#define NSTG 3

__device__ __forceinline__ void gemm_body(
    const float* __restrict__ A, const float* __restrict__ W,
    const float* __restrict__ bias, const float* __restrict__ res,
    float* __restrict__ C, int N, int K, int mode, int bm, int bn,
    float (&As)[NSTG][128][AST], float (&Bs)[NSTG][16][BST])
{
    int t = threadIdx.x;
    int lane = t & 31, wid = t >> 5;
    int r = lane >> 2, q = lane & 3;
    int m_base = (wid & 3) * 32;
    int n_base = (wid >> 2) * 64;

    int a_row0 = t >> 2;
    int a_kc   = (t & 3) * 4;
    int b_row0 = t >> 5;
    int b_col  = (t & 31) * 4;

    const int nk = K / 16;

    const float* Abase  = A + (size_t)(bm + a_row0) * K + a_kc;
    const float* Abase2 = Abase + (size_t)64 * K;
    const float* Wbase  = W + (size_t)b_row0 * N + bn + b_col;
    const float* Wbase2 = Wbase + (size_t)8 * N;

    float acc[2][8][4];
    #pragma unroll
    for (int i = 0; i < 2; i++)
        #pragma unroll
        for (int j = 0; j < 8; j++)
            #pragma unroll
            for (int c = 0; c < 4; c++) acc[i][j][c] = 0.f;

    #pragma unroll
    for (int s = 0; s < 2; s++) {
        int k0 = s * 16;
        cp_async16(&As[s][a_row0     ][a_kc], Abase  + k0);
        cp_async16(&As[s][a_row0 + 64][a_kc], Abase2 + k0);
        cp_async16(&Bs[s][b_row0     ][b_col], Wbase  + (size_t)k0 * N);
        cp_async16(&Bs[s][b_row0 + 8 ][b_col], Wbase2 + (size_t)k0 * N);
        cp_commit();
    }
    cp_wait<1>();
    __syncthreads();

    for (int kt = 0; kt < nk; kt++) {
        int buf = kt % NSTG;

        #pragma unroll
        for (int k8 = 0; k8 < 16; k8 += 8) {
            uint32_t a[2][4], b[8][2];
            #pragma unroll
            for (int mt = 0; mt < 2; mt++) {
                int m0 = m_base + mt * 16;
                a[mt][0] = __float_as_uint(As[buf][m0 + r    ][k8 + q]);
                a[mt][1] = __float_as_uint(As[buf][m0 + r + 8][k8 + q]);
                a[mt][2] = __float_as_uint(As[buf][m0 + r    ][k8 + q + 4]);
                a[mt][3] = __float_as_uint(As[buf][m0 + r + 8][k8 + q + 4]);
            }
            #pragma unroll
            for (int nt = 0; nt < 8; nt++) {
                int n0 = n_base + nt * 8;
                b[nt][0] = __float_as_uint(Bs[buf][k8 + q    ][n0 + r]);
                b[nt][1] = __float_as_uint(Bs[buf][k8 + q + 4][n0 + r]);
            }
            #pragma unroll
            for (int mt = 0; mt < 2; mt++)
                #pragma unroll
                for (int nt = 0; nt < 8; nt++)
                    mma_tf32(acc[mt][nt], a[mt], b[nt]);
        }

        if (kt + 2 < nk) {
            int s  = (kt + 2) % NSTG;
            int k0 = (kt + 2) * 16;
            cp_async16(&As[s][a_row0     ][a_kc], Abase  + k0);
            cp_async16(&As[s][a_row0 + 64][a_kc], Abase2 + k0);
            cp_async16(&Bs[s][b_row0     ][b_col], Wbase  + (size_t)k0 * N);
            cp_async16(&Bs[s][b_row0 + 8 ][b_col], Wbase2 + (size_t)k0 * N);
        }
        cp_commit();
        cp_wait<1>();
        __syncthreads();
    }

    #pragma unroll
    for (int mt = 0; mt < 2; mt++) {
        int row0 = bm + m_base + mt * 16 + r;
        #pragma unroll
        for (int nt = 0; nt < 8; nt++) {
            int col = bn + n_base + nt * 8 + q * 2;
            float b0 = bias[col], b1 = bias[col + 1];
            float r0 = 0.f, r1 = 0.f, r2 = 0.f, r3 = 0.f;
            if (mode == 1 || mode == 4) {
                r0 = res[(size_t)row0 * N + col];
                r1 = res[(size_t)row0 * N + col + 1];
                r2 = res[(size_t)(row0 + 8) * N + col];
                r3 = res[(size_t)(row0 + 8) * N + col + 1];
            }
            float v0 = epilogue_apply(acc[mt][nt][0] + b0, r0, mode);
            float v1 = epilogue_apply(acc[mt][nt][1] + b1, r1, mode);
            float v2 = epilogue_apply(acc[mt][nt][2] + b0, r2, mode);
            float v3 = epilogue_apply(acc[mt][nt][3] + b1, r3, mode);
            *(float2*)(C + (size_t)row0 * N + col)       = make_float2(v0, v1);
            *(float2*)(C + (size_t)(row0 + 8) * N + col) = make_float2(v2, v3);
        }
    }
}

// generic single-GEMM kernel
__global__ __launch_bounds__(256) void tgemm_kernel(
    const float* __restrict__ A, const float* __restrict__ W,
    const float* __restrict__ bias, const float* __restrict__ res,
    float* __restrict__ C, int N, int K, int mode)
{
    __shared__ float As[NSTG][128][AST];
    __shared__ float Bs[NSTG][16][BST];
    gemm_body(A, W, bias, res, C, N, K, mode, blockIdx.y * 128, blockIdx.x * 128, As, Bs);
}

// fused Q/K/V projection: grid.x = 4 + 4 + 12 = 20 column-tiles
__global__ __launch_bounds__(256) void qkv_kernel(
    const float* __restrict__ x1,
    const float* __restrict__ wq, const float* __restrict__ bq, float* __restrict__ qp,
    const float* __restrict__ wk, const float* __restrict__ bk, float* __restrict__ kp,
    const float* __restrict__ wv, const float* __restrict__ bv, float* __restrict__ vp)
{
    __shared__ float As[NSTG][128][AST];
    __shared__ float Bs[NSTG][16][BST];
    int bx = blockIdx.x, bm = blockIdx.y * 128;
    if (bx < 4)
        gemm_body(x1, wq, bq, nullptr, qp, DCc, Dd, 0, bm, bx * 128, As, Bs);
    else if (bx < 8)
        gemm_body(x1, wk, bk, nullptr, kp, DCc, Dd, 0, bm, (bx - 4) * 128, As, Bs);
    else
        gemm_body(x1, wv, bv, nullptr, vp, DMm, Dd, 0, bm, (bx - 8) * 128, As, Bs);
}

// fused FFN stage 1: e = x2@we+be (cols 0..31), sg = silu(x2@wg+bg) (cols 32..39)
__global__ __launch_bounds__(256) void ffn1_kernel(
    const float* __restrict__ x2,
    const float* __restrict__ we, const float* __restrict__ be, float* __restrict__ ep,
    const float* __restrict__ wg, const float* __restrict__ bg, float* __restrict__ sgp)
{
    __shared__ float As[NSTG][128][AST];
    __shared__ float Bs[NSTG][16][BST];
    int bx = blockIdx.x, bm = blockIdx.y * 128;
    if (bx < 32)
        gemm_body(x2, we, be, nullptr, ep, DEe, Dd, 0, bm, bx * 128, As, Bs);
    else
        gemm_body(x2, wg, bg, nullptr, sgp, DGg, Dd, 2, bm, (bx - 32) * 128, As, Bs);
}

// ---------------------------------------------------------------------------
// TF32 MMA flash attention (cvt-free)
// ---------------------------------------------------------------------------
#define AT_KST 36
#define AT_VST 68
#define AT_SST 68
#define ATTN_SMEM ((64*AT_KST + 96*AT_VST + 4*16*AT_SST) * 4)

__global__ __launch_bounds__(128) void attn_mma_kernel(
    const float* __restrict__ q, const float* __restrict__ k,
    const float* __restrict__ v, float* __restrict__ y)
{
    extern __shared__ float sm[];
    float* Ks = sm;
    float* Vs = Ks + 64 * AT_KST;
    float* Ss = Vs + 96 * AT_VST;

    int tid  = threadIdx.x;
    int wid  = tid >> 5, lane = tid & 31;
    int r    = lane >> 2, qd = lane & 3;
    int qt   = blockIdx.x;
    int bh   = blockIdx.y;
    int b    = bh >> 4, h = bh & 15;
    int q0   = qt * 64;
    int mrow = wid * 16;

    const float* qbase = q + (size_t)b * Tt * DCc + h * CHD;
    const float* kbase = k + (size_t)b * Tt * DCc + h * CHD;
    const float* vbase = v + (size_t)b * Tt * DMm + h * MHD;

    const float scale = 0.17677669529663687f;
    int grow0 = q0 + mrow + r;
    uint32_t qa[4][4];
    #pragma unroll
    for (int ks = 0; ks < 4; ks++) {
        qa[ks][0] = __float_as_uint(qbase[(size_t)grow0       * DCc + ks * 8 + qd    ] * scale);
        qa[ks][1] = __float_as_uint(qbase[(size_t)(grow0 + 8) * DCc + ks * 8 + qd    ] * scale);
        qa[ks][2] = __float_as_uint(qbase[(size_t)grow0       * DCc + ks * 8 + qd + 4] * scale);
        qa[ks][3] = __float_as_uint(qbase[(size_t)(grow0 + 8) * DCc + ks * 8 + qd + 4] * scale);
    }

    float m0 = -1e30f, m1 = -1e30f, l0 = 0.f, l1 = 0.f;
    float o[12][4];
    #pragma unroll
    for (int nt = 0; nt < 12; nt++)
        #pragma unroll
        for (int c = 0; c < 4; c++) o[nt][c] = 0.f;

    float* Sw = Ss + wid * 16 * AT_SST;

    for (int j = 0; j <= qt; j++) {
        int k0 = j * 64;
        __syncthreads();
        {
            int row = tid >> 1;
            int c0  = (tid & 1) * 16;
            const float* src = kbase + (size_t)(k0 + row) * DCc + c0;
            float* dst = &Ks[row * AT_KST + c0];
            #pragma unroll
            for (int jj = 0; jj < 4; jj++) {
                float4 f = *(const float4*)(src + jj * 4);
                *(float4*)(dst + jj * 4) = f;
            }
        }
        {
            #pragma unroll
            for (int it = 0; it < 12; it++) {
                int idx  = it * 128 + tid;
                int trow = idx / 24, c4 = idx % 24;
                float4 f = *(const float4*)(vbase + (size_t)(k0 + trow) * DMm + c4 * 4);
                Vs[(c4 * 4 + 0) * AT_VST + trow] = f.x;
                Vs[(c4 * 4 + 1) * AT_VST + trow] = f.y;
                Vs[(c4 * 4 + 2) * AT_VST + trow] = f.z;
                Vs[(c4 * 4 + 3) * AT_VST + trow] = f.w;
            }
        }
        __syncthreads();

        float sc[8][4];
        #pragma unroll
        for (int nt = 0; nt < 8; nt++)
            #pragma unroll
            for (int c = 0; c < 4; c++) sc[nt][c] = 0.f;
        #pragma unroll
        for (int ks = 0; ks < 4; ks++) {
            #pragma unroll
            for (int nt = 0; nt < 8; nt++) {
                uint32_t bb[2];
                bb[0] = __float_as_uint(Ks[(nt * 8 + r) * AT_KST + ks * 8 + qd    ]);
                bb[1] = __float_as_uint(Ks[(nt * 8 + r) * AT_KST + ks * 8 + qd + 4]);
                mma_tf32(sc[nt], qa[ks], bb);
            }
        }

        float mx0 = -1e30f, mx1 = -1e30f;
        #pragma unroll
        for (int nt = 0; nt < 8; nt++) {
            int c = k0 + nt * 8 + 2 * qd;
            if (c     > grow0    ) sc[nt][0] = -1e30f;
            if (c + 1 > grow0    ) sc[nt][1] = -1e30f;
            if (c     > grow0 + 8) sc[nt][2] = -1e30f;
            if (c + 1 > grow0 + 8) sc[nt][3] = -1e30f;
            mx0 = fmaxf(mx0, fmaxf(sc[nt][0], sc[nt][1]));
            mx1 = fmaxf(mx1, fmaxf(sc[nt][2], sc[nt][3]));
        }
        mx0 = fmaxf(mx0, __shfl_xor_sync(0xffffffffu, mx0, 1));
        mx0 = fmaxf(mx0, __shfl_xor_sync(0xffffffffu, mx0, 2));
        mx1 = fmaxf(mx1, __shfl_xor_sync(0xffffffffu, mx1, 1));
        mx1 = fmaxf(mx1, __shfl_xor_sync(0xffffffffu, mx1, 2));

        float mn0 = fmaxf(m0, mx0), mn1 = fmaxf(m1, mx1);
        float corr0 = __expf(m0 - mn0), corr1 = __expf(m1 - mn1);
        float s0 = 0.f, s1 = 0.f;
        #pragma unroll
        for (int nt = 0; nt < 8; nt++) {
            float p00 = __expf(sc[nt][0] - mn0);
            float p01 = __expf(sc[nt][1] - mn0);
            float p10 = __expf(sc[nt][2] - mn1);
            float p11 = __expf(sc[nt][3] - mn1);
            s0 += p00 + p01;
            s1 += p10 + p11;
            int cb = nt * 8 + 2 * qd;
            Sw[r * AT_SST + cb]           = p00;
            Sw[r * AT_SST + cb + 1]       = p01;
            Sw[(r + 8) * AT_SST + cb]     = p10;
            Sw[(r + 8) * AT_SST + cb + 1] = p11;
        }
        s0 += __shfl_xor_sync(0xffffffffu, s0, 1);
        s0 += __shfl_xor_sync(0xffffffffu, s0, 2);
        s1 += __shfl_xor_sync(0xffffffffu, s1, 1);
        s1 += __shfl_xor_sync(0xffffffffu, s1, 2);
        l0 = l0 * corr0 + s0;
        l1 = l1 * corr1 + s1;
        m0 = mn0; m1 = mn1;
        #pragma unroll
        for (int nt = 0; nt < 12; nt++) {
            o[nt][0] *= corr0; o[nt][1] *= corr0;
            o[nt][2] *= corr1; o[nt][3] *= corr1;
        }
        __syncwarp();

        #pragma unroll
        for (int ks = 0; ks < 8; ks++) {
            uint32_t pa[4];
            pa[0] = __float_as_uint(Sw[r       * AT_SST + ks * 8 + qd    ]);
            pa[1] = __float_as_uint(Sw[(r + 8) * AT_SST + ks * 8 + qd    ]);
            pa[2] = __float_as_uint(Sw[r       * AT_SST + ks * 8 + qd + 4]);
            pa[3] = __float_as_uint(Sw[(r + 8) * AT_SST + ks * 8 + qd + 4]);
            #pragma unroll
            for (int nt = 0; nt < 12; nt++) {
                uint32_t bb[2];
                bb[0] = __float_as_uint(Vs[(nt * 8 + r) * AT_VST + ks * 8 + qd    ]);
                bb[1] = __float_as_uint(Vs[(nt * 8 + r) * AT_VST + ks * 8 + qd + 4]);
                mma_tf32(o[nt], pa, bb);
            }
        }
        __syncwarp();
    }

    float inv0 = 1.f / l0, inv1 = 1.f / l1;
    float* yb = y + (size_t)b * Tt * DMm + h * MHD;
    #pragma unroll
    for (int nt = 0; nt < 12; nt++) {
        int cb = nt * 8 + 2 * qd;
        *(float2*)(yb + (size_t)grow0 * DMm + cb) =
            make_float2(o[nt][0] * inv0, o[nt][1] * inv0);
        *(float2*)(yb + (size_t)(grow0 + 8) * DMm + cb) =
            make_float2(o[nt][2] * inv1, o[nt][3] * inv1);
    }
}

// ---------------------------------------------------------------------------
// Host launcher
// ---------------------------------------------------------------------------
extern "C" void kernel_launch(void* const* d_in, const int* in_sizes, int n_in,
                              void* d_out, int out_size)
{
    const float* x     = (const float*)d_in[0];
    const float* ln1_w = (const float*)d_in[2];
    const float* ln1_b = (const float*)d_in[3];
    const float* wq    = (const float*)d_in[4];
    const float* bq    = (const float*)d_in[5];
    const float* wk    = (const float*)d_in[6];
    const float* bk    = (const float*)d_in[7];
    const float* wv    = (const float*)d_in[8];
    const float* bv    = (const float*)d_in[9];
    const float* wo    = (const float*)d_in[10];
    const float* bo    = (const float*)d_in[11];
    const float* ln2_w = (const float*)d_in[12];
    const float* ln2_b = (const float*)d_in[13];
    const float* we    = (const float*)d_in[14];
    const float* be    = (const float*)d_in[15];
    const float* wg    = (const float*)d_in[16];
    const float* bg    = (const float*)d_in[17];
    const float* wu    = (const float*)d_in[18];
    const float* bu    = (const float*)d_in[19];
    const float* wc    = (const float*)d_in[20];
    const float* bc    = (const float*)d_in[21];
    float* out = (float*)d_out;

    float *x1, *qp, *kp, *vp, *yp, *xa, *x2, *ep, *sg;
    cudaGetSymbolAddress((void**)&x1, g_x1);
    cudaGetSymbolAddress((void**)&qp, g_q);
    cudaGetSymbolAddress((void**)&kp, g_k);
    cudaGetSymbolAddress((void**)&vp, g_v);
    cudaGetSymbolAddress((void**)&yp, g_y);
    cudaGetSymbolAddress((void**)&xa, g_xa);
    cudaGetSymbolAddress((void**)&x2, g_x2);
    cudaGetSymbolAddress((void**)&ep, g_e);
    cudaGetSymbolAddress((void**)&sg, g_sg);

    cudaFuncSetAttribute(attn_mma_kernel,
                         cudaFuncAttributeMaxDynamicSharedMemorySize, ATTN_SMEM);

    // 1) LN1
    ln_kernel<<<Mrows, 256>>>(x, ln1_w, ln1_b, x1);

    // 2) fused Q/K/V projections (one launch, 640 CTAs)
    qkv_kernel<<<dim3(20, Mrows/128), 256>>>(x1, wq, bq, qp, wk, bk, kp, wv, bv, vp);

    // 3) causal attention (TF32 MMA)
    attn_mma_kernel<<<dim3(Tt/64, Bq*Hh), 128, ATTN_SMEM>>>(qp, kp, vp, yp);

    // 4) output projection + residual
    tgemm_kernel<<<dim3(Dd/128, Mrows/128), 256>>>(yp, wo, bo, x, xa, Dd, DMm, 1);

    // 5) LN2
    ln_kernel<<<Mrows, 256>>>(xa, ln2_w, ln2_b, x2);

    // 6) fused e = x2@we+be  AND  sg = silu(x2@wg+bg)  (one launch)
    ffn1_kernel<<<dim3(40, Mrows/128), 256>>>(x2, we, be, ep, wg, bg, sg);

    // 7) e = silu(e * sigmoid(sg@wu + bu))   [fused eg epilogue]
    tgemm_kernel<<<dim3(DEe/128, Mrows/128), 256>>>(sg, wu, bu, ep, ep, DEe, DGg, 4);

    // 8) out = xa + e@wc + bc
    tgemm_kernel<<<dim3(Dd/128, Mrows/128), 256>>>(ep, wc, bc, xa, out, Dd, DEe, 1);
}